// round 8
// baseline (speedup 1.0000x reference)
#include <cuda_runtime.h>
#include <math.h>
#include <stdint.h>

#define BB 4
#define CC 64
#define NP 8192
#define OO 128
#define KNN 20

// ---------------- device scratch ----------------
__device__ float g_xt[(size_t)BB * NP * CC];        // x transposed: [b][n][c]
__device__ float g_xxn[BB * NP];                    // -0.5*||x||^2
__device__ float g_uvq[(size_t)BB * NP * 256];      // [b][n][ U(64) | V(64) | Q(128) ]
__device__ int   g_idx[(size_t)BB * NP * KNN];      // top-20 neighbor indices

__device__ __forceinline__ void ffma2(unsigned long long& d,
                                      unsigned long long a,
                                      unsigned long long b) {
    asm("fma.rn.f32x2 %0, %1, %2, %0;" : "+l"(d) : "l"(a), "l"(b));
}
__device__ __forceinline__ void fadd2(unsigned long long& d,
                                      unsigned long long b) {
    asm("add.rn.f32x2 %0, %0, %1;" : "+l"(d) : "l"(b));
}
__device__ __forceinline__ unsigned long long packdup(float v) {
    unsigned long long r;
    asm("mov.b64 %0, {%1, %1};" : "=l"(r) : "f"(v));
    return r;
}

// ---------------- K0: transpose x (B,C,N) -> xt (B,N,C) ----------------
__global__ void k_transpose(const float* __restrict__ x) {
    __shared__ float tile[32][33];
    int b  = blockIdx.z;
    int c0 = blockIdx.y * 32;
    int n0 = blockIdx.x * 32;
    int tx = threadIdx.x, ty = threadIdx.y;   // 32 x 8
#pragma unroll
    for (int yy = 0; yy < 32; yy += 8)
        tile[ty + yy][tx] = x[((size_t)b * CC + c0 + ty + yy) * NP + n0 + tx];
    __syncthreads();
#pragma unroll
    for (int yy = 0; yy < 32; yy += 8)
        g_xt[((size_t)b * NP + n0 + ty + yy) * CC + c0 + tx] = tile[tx][ty + yy];
}

// ---------------- K0b: negated half squared norms ----------------
__global__ void k_norm() {
    int p = blockIdx.x * blockDim.x + threadIdx.x;
    const float4* v = (const float4*)&g_xt[(size_t)p * CC];
    float s = 0.f;
#pragma unroll
    for (int i = 0; i < 16; i++) {
        float4 q = v[i];
        s += q.x * q.x + q.y * q.y + q.z * q.z + q.w * q.w;
    }
    g_xxn[p] = -0.5f * s;
}

// ---------------- K1: precompute U, V, Q per point ----------------
__global__ __launch_bounds__(256) void k_uvq(const float* __restrict__ W1,
                                             const float* __restrict__ W2) {
    __shared__ float xts[16][64];
    int p0 = blockIdx.x * 16;
    int o  = threadIdx.x;
    for (int s = threadIdx.x; s < 16 * 64; s += 256)
        xts[s >> 6][s & 63] = g_xt[(size_t)p0 * 64 + s];

    float4 wr[16];
    if (o < 64) {
        const float* r = W1 + o * 128;
#pragma unroll
        for (int i = 0; i < 16; i++)
            wr[i] = make_float4(r[4*i], r[4*i+1], r[4*i+2], r[4*i+3]);
    } else if (o < 128) {
        const float* r = W1 + (o - 64) * 128;
#pragma unroll
        for (int i = 0; i < 16; i++)
            wr[i] = make_float4(r[64+4*i]-r[4*i], r[65+4*i]-r[4*i+1],
                                r[66+4*i]-r[4*i+2], r[67+4*i]-r[4*i+3]);
    } else {
        const float* r = W2 + (o - 128) * 128;
#pragma unroll
        for (int i = 0; i < 16; i++)
            wr[i] = make_float4(r[64+4*i]-r[4*i], r[65+4*i]-r[4*i+1],
                                r[66+4*i]-r[4*i+2], r[67+4*i]-r[4*i+3]);
    }
    __syncthreads();

    float acc[16];
#pragma unroll
    for (int p = 0; p < 16; p++) acc[p] = 0.f;
#pragma unroll
    for (int c4 = 0; c4 < 16; c4++) {
        float4 w = wr[c4];
#pragma unroll
        for (int p = 0; p < 16; p++) {
            float4 xv = *(const float4*)&xts[p][c4 * 4];
            acc[p] += w.x * xv.x + w.y * xv.y + w.z * xv.z + w.w * xv.w;
        }
    }
#pragma unroll
    for (int p = 0; p < 16; p++)
        g_uvq[((size_t)p0 + p) * 256 + o] = acc[p];
}

// ---------------- K2: kNN top-20, 128x128 tile, 8x8 packed micro-tile ----------------
// Rank value v(i,j) = dot(xi,xj) - 0.5*xx_j  (monotone in -dist^2)
// xj staged in 32-c chunks; xi fully resident; smem ~69.6KB -> 3 blocks/SM.
#define TI 128
#define TJ 128
#define XI_OFF 0                        // [c][i] 64 x 132 = 8448
#define XJ_OFF 8448                     // [c][j] 32 x 132 = 4224 (one c-chunk)
#define DS_OFF 12672                    // 128 x 36 = 4608
#define XXN_OFF 17280                   // 128
#define SMF 17408
#define KNN_SMEM_BYTES (SMF * 4)

#define INS(val, jj)                                              \
    do {                                                          \
        float _v = (val);                                         \
        if (_v > minv) {                                          \
            bv[minp] = _v; bi[minp] = (jj);                       \
            minv = bv[0]; minp = 0;                               \
            for (int _t = 1; _t < KNN; _t++)                      \
                if (bv[_t] < minv) { minv = bv[_t]; minp = _t; }  \
        }                                                         \
    } while (0)

__global__ void __launch_bounds__(256, 3) k_knn(const float* __restrict__ x) {
    extern __shared__ float sm[];
    float* xi  = sm + XI_OFF;
    float* xj  = sm + XJ_OFF;
    float* Ds  = sm + DS_OFF;
    float* xxn = sm + XXN_OFF;

    int b   = blockIdx.y;
    int i0  = blockIdx.x * TI;
    int tid = threadIdx.x;
    int ty  = tid >> 4;                 // 0..15 -> rows 8ty..8ty+7
    int tx  = tid & 15;                 // 0..15 -> cols 8tx..8tx+7
    size_t base = (size_t)b * NP;
    const float* xb = x + (size_t)b * CC * NP;   // c-major [c][n]

    // xi: [c][i] for all 64 c, once (coalesced from input)
#pragma unroll
    for (int m = 0; m < 8; m++) {
        int s  = tid + 256 * m;         // 0..2047
        int c  = s >> 5;                // 0..63
        int i4 = (s & 31) << 2;         // 0..124
        *(float4*)&xi[c * 132 + i4] = *(const float4*)&xb[(size_t)c * NP + i0 + i4];
    }

    float bv[KNN]; int bi[KNN];
    float minv = -3.4e38f; int minp = 0;
    for (int t = 0; t < KNN; t++) { bv[t] = -3.4e38f; bi[t] = 0; }

    const float* pa = xi + 8 * ty;
    const float* pb = xj + 8 * tx;
    int qsel = tx >> 2;                 // which 32-col round this thread writes
    int lc   = 8 * (tx & 3);            // col offset within round

    for (int jt = 0; jt < NP; jt += TJ) {
        unsigned long long acc[8][4];
#pragma unroll
        for (int i = 0; i < 8; i++)
#pragma unroll
            for (int p = 0; p < 4; p++) acc[i][p] = 0ULL;

#pragma unroll
        for (int h = 0; h < 2; h++) {
            __syncthreads();            // prior xj/Ds reads done
            // xj chunk: c in [32h, 32h+32)
#pragma unroll
            for (int m = 0; m < 4; m++) {
                int s  = tid + 256 * m; // 0..1023
                int c  = s >> 5;        // 0..31
                int j4 = (s & 31) << 2;
                *(float4*)&xj[c * 132 + j4] =
                    *(const float4*)&xb[(size_t)(32 * h + c) * NP + jt + j4];
            }
            if (h == 0 && tid < 32)
                *(float4*)&xxn[4 * tid] = *(const float4*)&g_xxn[base + jt + 4 * tid];
            __syncthreads();

            const float* pah = pa + (32 * h) * 132;
#pragma unroll 4
            for (int c = 0; c < 32; c++) {
                float4 a0 = *(const float4*)(pah + c * 132);
                float4 a1 = *(const float4*)(pah + c * 132 + 4);
                ulonglong2 b0 = *(const ulonglong2*)(pb + c * 132);
                ulonglong2 b1 = *(const ulonglong2*)(pb + c * 132 + 4);
                unsigned long long A[8];
                A[0] = packdup(a0.x); A[1] = packdup(a0.y);
                A[2] = packdup(a0.z); A[3] = packdup(a0.w);
                A[4] = packdup(a1.x); A[5] = packdup(a1.y);
                A[6] = packdup(a1.z); A[7] = packdup(a1.w);
#pragma unroll
                for (int i = 0; i < 8; i++) {
                    ffma2(acc[i][0], A[i], b0.x);
                    ffma2(acc[i][1], A[i], b0.y);
                    ffma2(acc[i][2], A[i], b1.x);
                    ffma2(acc[i][3], A[i], b1.y);
                }
            }
        }

        // 4 rounds of 32 cols: writers = threads with tx>>2 == q
#pragma unroll
        for (int q = 0; q < 4; q++) {
            if (qsel == q) {
                ulonglong2 n0 = *(const ulonglong2*)&xxn[8 * tx];
                ulonglong2 n1 = *(const ulonglong2*)&xxn[8 * tx + 4];
#pragma unroll
                for (int i = 0; i < 8; i++) {
                    unsigned long long s0 = acc[i][0], s1 = acc[i][1];
                    unsigned long long s2 = acc[i][2], s3 = acc[i][3];
                    fadd2(s0, n0.x); fadd2(s1, n0.y);
                    fadd2(s2, n1.x); fadd2(s3, n1.y);
                    union { unsigned long long u[2]; float4 f; } U0, U1;
                    U0.u[0] = s0; U0.u[1] = s1;
                    U1.u[0] = s2; U1.u[1] = s3;
                    int row = 8 * ty + i;
                    *(float4*)&Ds[row * 36 + lc]     = U0.f;
                    *(float4*)&Ds[row * 36 + lc + 4] = U1.f;
                }
            }
            __syncthreads();
            {
                int row = tid >> 1, sub = tid & 1;
                int jb = jt + 32 * q + 16 * sub;
                const float* p = &Ds[row * 36 + 16 * sub];
#pragma unroll
                for (int m = 0; m < 4; m++) {
                    float4 v = *(const float4*)(p + 4 * m);
                    INS(v.x, jb + 4 * m + 0);
                    INS(v.y, jb + 4 * m + 1);
                    INS(v.z, jb + 4 * m + 2);
                    INS(v.w, jb + 4 * m + 3);
                }
            }
            if (q < 3) __syncthreads();   // last round's barrier folds into next tile's
        }
    }

    // merge: 2 partial lists per row -> exact top-20
    __syncthreads();
    float* cv = sm;                       // 256*20
    int*   ci = (int*)(sm + 5120);        // 256*20
    for (int t = 0; t < KNN; t++) {
        cv[tid * KNN + t] = bv[t];
        ci[tid * KNN + t] = bi[t];
    }
    __syncthreads();
    if (tid < TI) {
        float fv[KNN]; int fi[KNN];
        float mv = -3.4e38f; int mp = 0;
        for (int t = 0; t < KNN; t++) { fv[t] = -3.4e38f; fi[t] = 0; }
        for (int u = 0; u < 2; u++) {
            int src = (tid * 2 + u) * KNN;
            for (int t = 0; t < KNN; t++) {
                float v = cv[src + t];
                if (v > mv) {
                    fv[mp] = v; fi[mp] = ci[src + t];
                    mv = fv[0]; mp = 0;
                    for (int w = 1; w < KNN; w++)
                        if (fv[w] < mv) { mv = fv[w]; mp = w; }
                }
            }
        }
        for (int t = 0; t < KNN; t++)
            g_idx[(base + i0 + tid) * KNN + t] = fi[t];
    }
}

// ---------------- K3: fused gather + softmax gate + output GEMM ----------------
__global__ __launch_bounds__(256) void k_fuse(const float* __restrict__ W2,
                                              float* __restrict__ out) {
    __shared__ float w2as[64 * 128];
    __shared__ float t_s[16][64];
    __shared__ int   idxs[16][KNN];

    int blk = blockIdx.x;
    int b   = blk >> 9;
    int n0  = (blk & 511) * 16;
    int tid = threadIdx.x;
    size_t base = (size_t)b * NP;

    for (int s = tid; s < 8192; s += 256) {
        int o = s >> 6, c = s & 63;
        w2as[c * 128 + o] = W2[o * 128 + c];
    }
    for (int s = tid; s < 16 * KNN; s += 256)
        idxs[s / KNN][s % KNN] = g_idx[(base + n0) * KNN + s];
    __syncthreads();

    for (int pass = 0; pass < 4; pass++) {
        int pt = pass * 4 + (tid >> 6);
        int d  = tid & 63;
        float vv = g_uvq[(base + n0 + pt) * 256 + 64 + d];
        float h[KNN];
#pragma unroll
        for (int k = 0; k < KNN; k++) {
            int j = idxs[pt][k];
            h[k] = g_uvq[(base + j) * 256 + d] + vv;
        }
        float m = h[0];
#pragma unroll
        for (int k = 1; k < KNN; k++) m = fmaxf(m, h[k]);
        float S = 0.f, ws = 0.f;
#pragma unroll
        for (int k = 0; k < KNN; k++) {
            float e = __expf(h[k] - m);
            S += e;
            int j = idxs[pt][k];
            ws += g_xt[(base + j) * 64 + d] * e;
        }
        t_s[pt][d] = ws / S;
    }
    __syncthreads();

    int o = tid & 127, g = tid >> 7;
    float acc[8];
#pragma unroll
    for (int p = 0; p < 8; p++)
        acc[p] = g_uvq[(base + n0 + g * 8 + p) * 256 + 128 + o];
#pragma unroll 8
    for (int c = 0; c < 64; c++) {
        float w = w2as[c * 128 + o];
#pragma unroll
        for (int p = 0; p < 8; p++) acc[p] += w * t_s[g * 8 + p][c];
    }
    float* op = out + ((size_t)b * OO + o) * NP + n0 + g * 8;
    *(float4*)op       = make_float4(acc[0], acc[1], acc[2], acc[3]);
    *(float4*)(op + 4) = make_float4(acc[4], acc[5], acc[6], acc[7]);
}

// ---------------- launch ----------------
extern "C" void kernel_launch(void* const* d_in, const int* in_sizes, int n_in,
                              void* d_out, int out_size) {
    const float* x  = (const float*)d_in[0];
    const float* W1 = (const float*)d_in[1];
    const float* W2 = (const float*)d_in[2];
    float* out = (float*)d_out;

    cudaFuncSetAttribute(k_knn, cudaFuncAttributeMaxDynamicSharedMemorySize,
                         KNN_SMEM_BYTES);

    k_transpose<<<dim3(NP / 32, CC / 32, BB), dim3(32, 8)>>>(x);
    k_norm<<<(BB * NP) / 256, 256>>>();
    k_uvq<<<(BB * NP) / 16, 256>>>(W1, W2);
    k_knn<<<dim3(NP / TI, BB), 256, KNN_SMEM_BYTES>>>(x);
    k_fuse<<<(BB * NP) / 16, 256>>>(W2, out);
}

// round 10
// speedup vs baseline: 1.9464x; 1.9464x over previous
#include <cuda_runtime.h>
#include <cuda_bf16.h>
#include <math.h>
#include <stdint.h>

#define BB 4
#define CC 64
#define NP 8192
#define OO 128
#define KNN 20

// ---------------- device scratch ----------------
__device__ float g_xt[(size_t)BB * NP * CC];          // x transposed: [b][n][c] fp32
__device__ __nv_bfloat16 g_xhi[(size_t)BB * NP * CC]; // bf16 hi part
__device__ __nv_bfloat16 g_xlo[(size_t)BB * NP * CC]; // bf16 lo part
__device__ float g_xxn[BB * NP];                      // -0.5*||x||^2
__device__ float g_uvq[(size_t)BB * NP * 256];        // [b][n][ U(64) | V(64) | Q(128) ]
__device__ int   g_idx[(size_t)BB * NP * KNN];        // top-20 neighbor indices

#define SWZ(off) ((off) ^ (((off) >> 3) & 0x70))

__device__ __forceinline__ void ldsm_x4(uint32_t* r, uint32_t addr) {
    asm volatile("ldmatrix.sync.aligned.m8n8.x4.shared.b16 {%0,%1,%2,%3}, [%4];"
                 : "=r"(r[0]), "=r"(r[1]), "=r"(r[2]), "=r"(r[3]) : "r"(addr));
}
__device__ __forceinline__ void mma16816(float* d, const uint32_t* a,
                                         uint32_t b0, uint32_t b1) {
    asm volatile(
        "mma.sync.aligned.m16n8k16.row.col.f32.bf16.bf16.f32 "
        "{%0,%1,%2,%3}, {%4,%5,%6,%7}, {%8,%9}, {%0,%1,%2,%3};"
        : "+f"(d[0]), "+f"(d[1]), "+f"(d[2]), "+f"(d[3])
        : "r"(a[0]), "r"(a[1]), "r"(a[2]), "r"(a[3]), "r"(b0), "r"(b1));
}

// ---------------- K0: transpose + bf16 hi/lo split ----------------
__global__ void k_transpose(const float* __restrict__ x) {
    __shared__ float tile[32][33];
    int b  = blockIdx.z;
    int c0 = blockIdx.y * 32;
    int n0 = blockIdx.x * 32;
    int tx = threadIdx.x, ty = threadIdx.y;   // 32 x 8
#pragma unroll
    for (int yy = 0; yy < 32; yy += 8)
        tile[ty + yy][tx] = x[((size_t)b * CC + c0 + ty + yy) * NP + n0 + tx];
    __syncthreads();
#pragma unroll
    for (int yy = 0; yy < 32; yy += 8) {
        float v = tile[tx][ty + yy];
        size_t off = ((size_t)b * NP + n0 + ty + yy) * CC + c0 + tx;
        g_xt[off] = v;
        __nv_bfloat16 h = __float2bfloat16(v);
        g_xhi[off] = h;
        g_xlo[off] = __float2bfloat16(v - __bfloat162float(h));
    }
}

// ---------------- K0b: negated half squared norms ----------------
__global__ void k_norm() {
    int p = blockIdx.x * blockDim.x + threadIdx.x;
    const float4* v = (const float4*)&g_xt[(size_t)p * CC];
    float s = 0.f;
#pragma unroll
    for (int i = 0; i < 16; i++) {
        float4 q = v[i];
        s += q.x * q.x + q.y * q.y + q.z * q.z + q.w * q.w;
    }
    g_xxn[p] = -0.5f * s;
}

// ---------------- K1: precompute U, V, Q per point ----------------
__global__ __launch_bounds__(256) void k_uvq(const float* __restrict__ W1,
                                             const float* __restrict__ W2) {
    __shared__ float xts[16][64];
    int p0 = blockIdx.x * 16;
    int o  = threadIdx.x;
    for (int s = threadIdx.x; s < 16 * 64; s += 256)
        xts[s >> 6][s & 63] = g_xt[(size_t)p0 * 64 + s];

    float4 wr[16];
    if (o < 64) {
        const float* r = W1 + o * 128;
#pragma unroll
        for (int i = 0; i < 16; i++)
            wr[i] = make_float4(r[4*i], r[4*i+1], r[4*i+2], r[4*i+3]);
    } else if (o < 128) {
        const float* r = W1 + (o - 64) * 128;
#pragma unroll
        for (int i = 0; i < 16; i++)
            wr[i] = make_float4(r[64+4*i]-r[4*i], r[65+4*i]-r[4*i+1],
                                r[66+4*i]-r[4*i+2], r[67+4*i]-r[4*i+3]);
    } else {
        const float* r = W2 + (o - 128) * 128;
#pragma unroll
        for (int i = 0; i < 16; i++)
            wr[i] = make_float4(r[64+4*i]-r[4*i], r[65+4*i]-r[4*i+1],
                                r[66+4*i]-r[4*i+2], r[67+4*i]-r[4*i+3]);
    }
    __syncthreads();

    float acc[16];
#pragma unroll
    for (int p = 0; p < 16; p++) acc[p] = 0.f;
#pragma unroll
    for (int c4 = 0; c4 < 16; c4++) {
        float4 w = wr[c4];
#pragma unroll
        for (int p = 0; p < 16; p++) {
            float4 xv = *(const float4*)&xts[p][c4 * 4];
            acc[p] += w.x * xv.x + w.y * xv.y + w.z * xv.z + w.w * xv.w;
        }
    }
#pragma unroll
    for (int p = 0; p < 16; p++)
        g_uvq[((size_t)p0 + p) * 256 + o] = acc[p];
}

// ---------------- K2: kNN top-20 via HMMA bf16 split-GEMM ----------------
// D = Ahi.Bhi^T + Ahi.Blo^T + Alo.Bhi^T  (~fp32 dot), rank = D - 0.5*xx_j.
// smem byte offsets
#define SA_HI 0          // 128 x 128B = 16384
#define SA_LO 16384
#define SB_HI 32768
#define SB_LO 49152
#define SXXN  65536      // 512 B
#define KNN_SMEM_BYTES 81920   // merge phase: cv 40960 @0, ci 40960 @40960

#define INSL(bvA, biA, mvA, mpA, val, jj)                               \
    do {                                                                \
        float _v = (val);                                               \
        if (_v > mvA) {                                                 \
            bvA[mpA] = _v; biA[mpA] = (jj);                             \
            mvA = bvA[0]; mpA = 0;                                      \
            for (int _t = 1; _t < KNN; _t++)                            \
                if (bvA[_t] < mvA) { mvA = bvA[_t]; mpA = _t; }         \
        }                                                               \
    } while (0)

// load a 128-row x 64-col bf16 tile (128B rows, SW128) into smem
__device__ __forceinline__ void load_tile_bf16(char* dst,
                                               const __nv_bfloat16* src,
                                               int t0) {
    for (int ch = t0; ch < 1024; ch += 256) {
        int row = ch >> 3, c16 = ch & 7;
        uint4 v = *(const uint4*)(src + (size_t)row * 64 + c16 * 8);
        uint32_t off = row * 128 + c16 * 16;
        *(uint4*)(dst + SWZ(off)) = v;
    }
}

__global__ void __launch_bounds__(256, 2) k_knn() {
    extern __shared__ char sm[];
    uint32_t smb;
    asm("{ .reg .u64 t; cvta.to.shared.u64 t, %1; cvt.u32.u64 %0, t; }"
        : "=r"(smb) : "l"(sm));

    int b    = blockIdx.y;
    int i0   = blockIdx.x * 128;
    int tid  = threadIdx.x;
    int wid  = tid >> 5;
    int lane = tid & 31;
    size_t base = (size_t)b * NP;

    // A tiles (hi+lo), resident all kernel
    load_tile_bf16(sm + SA_HI, g_xhi + (base + i0) * CC, tid);
    load_tile_bf16(sm + SA_LO, g_xlo + (base + i0) * CC, tid);

    // ldmatrix lane address offsets
    // A (x4): m0 rows0-7/k0, m1 rows8-15/k0, m2 rows0-7/k8, m3 rows8-15/k8
    int a_row = 16 * wid + (lane & 7) + 8 * ((lane >> 3) & 1);
    int a_k8  = (lane >> 4) * 8;
    // B (x4): m0 j0-7/k0, m1 j0-7/k8, m2 j8-15/k0, m3 j8-15/k8 (j rel. to 16p)
    int b_row = (lane & 7) + 8 * (lane >> 4);
    int b_k8  = ((lane >> 3) & 1) * 8;

    // two per-thread top-20 lists (rows r0, r1), local memory
    float bv0[KNN], bv1[KNN]; int bi0[KNN], bi1[KNN];
    float mv0 = -3.4e38f, mv1 = -3.4e38f; int mp0 = 0, mp1 = 0;
    for (int t = 0; t < KNN; t++) {
        bv0[t] = -3.4e38f; bi0[t] = 0;
        bv1[t] = -3.4e38f; bi1[t] = 0;
    }

    const float* xxn = (const float*)(sm + SXXN);
    int ncol = 2 * (lane & 3);          // this thread's col pair within n-group

    for (int t = 0; t < 64; t++) {
        __syncthreads();                // prior tile fully consumed
        load_tile_bf16(sm + SB_HI, g_xhi + (base + (size_t)t * 128) * CC, tid);
        load_tile_bf16(sm + SB_LO, g_xlo + (base + (size_t)t * 128) * CC, tid);
        if (tid < 32)
            *(float4*)(sm + SXXN + 16 * tid) =
                *(const float4*)&g_xxn[base + (size_t)t * 128 + 4 * tid];
        __syncthreads();

        float acc[16][4];
#pragma unroll
        for (int n = 0; n < 16; n++)
#pragma unroll
            for (int q = 0; q < 4; q++) acc[n][q] = 0.f;

#pragma unroll
        for (int kk = 0; kk < 4; kk++) {
            uint32_t ahi[4], alo[4];
            uint32_t a_off = SWZ((uint32_t)(a_row * 128 + (16 * kk + a_k8) * 2));
            ldsm_x4(ahi, smb + SA_HI + a_off);
            ldsm_x4(alo, smb + SA_LO + a_off);
#pragma unroll
            for (int p = 0; p < 8; p++) {
                uint32_t bh[4], bl[4];
                uint32_t b_off = SWZ((uint32_t)((16 * p + b_row) * 128 +
                                                (16 * kk + b_k8) * 2));
                ldsm_x4(bh, smb + SB_HI + b_off);
                ldsm_x4(bl, smb + SB_LO + b_off);
                mma16816(acc[2 * p],     ahi, bh[0], bh[1]);
                mma16816(acc[2 * p + 1], ahi, bh[2], bh[3]);
                mma16816(acc[2 * p],     ahi, bl[0], bl[1]);
                mma16816(acc[2 * p + 1], ahi, bl[2], bl[3]);
                mma16816(acc[2 * p],     alo, bh[0], bh[1]);
                mma16816(acc[2 * p + 1], alo, bh[2], bh[3]);
            }
        }

        // rank + insert straight from fragments
        int jt = t * 128;
#pragma unroll
        for (int n = 0; n < 16; n++) {
            float2 nx = *(const float2*)&xxn[8 * n + ncol];
            int jc = jt + 8 * n + ncol;
            float v0 = acc[n][0] + nx.x;
            float v1 = acc[n][1] + nx.y;
            float v2 = acc[n][2] + nx.x;
            float v3 = acc[n][3] + nx.y;
            if (fmaxf(v0, v1) > mv0) {
                INSL(bv0, bi0, mv0, mp0, v0, jc);
                INSL(bv0, bi0, mv0, mp0, v1, jc + 1);
            }
            if (fmaxf(v2, v3) > mv1) {
                INSL(bv1, bi1, mv1, mp1, v2, jc);
                INSL(bv1, bi1, mv1, mp1, v3, jc + 1);
            }
        }
    }

    // merge: 4 sub-lists per row -> exact top-20
    __syncthreads();
    float* cv = (float*)sm;              // 128 rows x 4 lists x 20
    int*   ci = (int*)(sm + 40960);
    {
        int r0 = 16 * wid + (lane >> 2);
        int r1 = r0 + 8;
        int s  = lane & 3;
        for (int t = 0; t < KNN; t++) {
            cv[(r0 * 4 + s) * KNN + t] = bv0[t];
            ci[(r0 * 4 + s) * KNN + t] = bi0[t];
            cv[(r1 * 4 + s) * KNN + t] = bv1[t];
            ci[(r1 * 4 + s) * KNN + t] = bi1[t];
        }
    }
    __syncthreads();
    if (tid < 128) {
        float fv[KNN]; int fi[KNN];
        float mv = -3.4e38f; int mp = 0;
        for (int t = 0; t < KNN; t++) { fv[t] = -3.4e38f; fi[t] = 0; }
        for (int u = 0; u < 4; u++) {
            int src = (tid * 4 + u) * KNN;
            for (int t = 0; t < KNN; t++) {
                float v = cv[src + t];
                if (v > mv) {
                    fv[mp] = v; fi[mp] = ci[src + t];
                    mv = fv[0]; mp = 0;
                    for (int w = 1; w < KNN; w++)
                        if (fv[w] < mv) { mv = fv[w]; mp = w; }
                }
            }
        }
        for (int t = 0; t < KNN; t++)
            g_idx[(base + i0 + tid) * KNN + t] = fi[t];
    }
}

// ---------------- K3: fused gather + softmax gate + output GEMM ----------------
__global__ __launch_bounds__(256) void k_fuse(const float* __restrict__ W2,
                                              float* __restrict__ out) {
    __shared__ float w2as[64 * 128];
    __shared__ float t_s[16][64];
    __shared__ int   idxs[16][KNN];

    int blk = blockIdx.x;
    int b   = blk >> 9;
    int n0  = (blk & 511) * 16;
    int tid = threadIdx.x;
    size_t base = (size_t)b * NP;

    for (int s = tid; s < 8192; s += 256) {
        int o = s >> 6, c = s & 63;
        w2as[c * 128 + o] = W2[o * 128 + c];
    }
    for (int s = tid; s < 16 * KNN; s += 256)
        idxs[s / KNN][s % KNN] = g_idx[(base + n0) * KNN + s];
    __syncthreads();

    for (int pass = 0; pass < 4; pass++) {
        int pt = pass * 4 + (tid >> 6);
        int d  = tid & 63;
        float vv = g_uvq[(base + n0 + pt) * 256 + 64 + d];
        float h[KNN];
#pragma unroll
        for (int k = 0; k < KNN; k++) {
            int j = idxs[pt][k];
            h[k] = g_uvq[(base + j) * 256 + d] + vv;
        }
        float m = h[0];
#pragma unroll
        for (int k = 1; k < KNN; k++) m = fmaxf(m, h[k]);
        float S = 0.f, ws = 0.f;
#pragma unroll
        for (int k = 0; k < KNN; k++) {
            float e = __expf(h[k] - m);
            S += e;
            int j = idxs[pt][k];
            ws += g_xt[(base + j) * 64 + d] * e;
        }
        t_s[pt][d] = ws / S;
    }
    __syncthreads();

    int o = tid & 127, g = tid >> 7;
    float acc[8];
#pragma unroll
    for (int p = 0; p < 8; p++)
        acc[p] = g_uvq[(base + n0 + g * 8 + p) * 256 + 128 + o];
#pragma unroll 8
    for (int c = 0; c < 64; c++) {
        float w = w2as[c * 128 + o];
#pragma unroll
        for (int p = 0; p < 8; p++) acc[p] += w * t_s[g * 8 + p][c];
    }
    float* op = out + ((size_t)b * OO + o) * NP + n0 + g * 8;
    *(float4*)op       = make_float4(acc[0], acc[1], acc[2], acc[3]);
    *(float4*)(op + 4) = make_float4(acc[4], acc[5], acc[6], acc[7]);
}

// ---------------- launch ----------------
extern "C" void kernel_launch(void* const* d_in, const int* in_sizes, int n_in,
                              void* d_out, int out_size) {
    const float* x  = (const float*)d_in[0];
    const float* W1 = (const float*)d_in[1];
    const float* W2 = (const float*)d_in[2];
    float* out = (float*)d_out;

    cudaFuncSetAttribute(k_knn, cudaFuncAttributeMaxDynamicSharedMemorySize,
                         KNN_SMEM_BYTES);

    k_transpose<<<dim3(NP / 32, CC / 32, BB), dim3(32, 8)>>>(x);
    k_norm<<<(BB * NP) / 256, 256>>>();
    k_uvq<<<(BB * NP) / 16, 256>>>(W1, W2);
    k_knn<<<dim3(NP / 128, BB), 256, KNN_SMEM_BYTES>>>();
    k_fuse<<<(BB * NP) / 16, 256>>>(W2, out);
}

// round 15
// speedup vs baseline: 2.0106x; 1.0330x over previous
#include <cuda_runtime.h>
#include <cuda_bf16.h>
#include <math.h>
#include <stdint.h>

#define BB 4
#define CC 64
#define NP 8192
#define OO 128
#define KNN 20

// ---------------- device scratch ----------------
__device__ float g_xt[(size_t)BB * NP * CC];          // x transposed: [b][n][c] fp32
__device__ __nv_bfloat16 g_xhi[(size_t)BB * NP * CC]; // bf16 hi part
__device__ __nv_bfloat16 g_xlo[(size_t)BB * NP * CC]; // bf16 lo part
__device__ float g_xxn[BB * NP];                      // -0.5*||x||^2
__device__ float g_uvq[(size_t)BB * NP * 256];        // [b][n][ U(64) | V(64) | Q(128) ]
__device__ int   g_idx[(size_t)BB * NP * KNN];        // top-20 neighbor indices

#define SWZ(off) ((off) ^ (((off) >> 3) & 0x70))

__device__ __forceinline__ void ldsm_x4(uint32_t* r, uint32_t addr) {
    asm volatile("ldmatrix.sync.aligned.m8n8.x4.shared.b16 {%0,%1,%2,%3}, [%4];"
                 : "=r"(r[0]), "=r"(r[1]), "=r"(r[2]), "=r"(r[3]) : "r"(addr));
}
__device__ __forceinline__ void mma16816(float* d, const uint32_t* a,
                                         uint32_t b0, uint32_t b1) {
    asm volatile(
        "mma.sync.aligned.m16n8k16.row.col.f32.bf16.bf16.f32 "
        "{%0,%1,%2,%3}, {%4,%5,%6,%7}, {%8,%9}, {%0,%1,%2,%3};"
        : "+f"(d[0]), "+f"(d[1]), "+f"(d[2]), "+f"(d[3])
        : "r"(a[0]), "r"(a[1]), "r"(a[2]), "r"(a[3]), "r"(b0), "r"(b1));
}

// ---------------- K0: transpose + bf16 hi/lo split ----------------
__global__ void k_transpose(const float* __restrict__ x) {
    __shared__ float tile[32][33];
    int b  = blockIdx.z;
    int c0 = blockIdx.y * 32;
    int n0 = blockIdx.x * 32;
    int tx = threadIdx.x, ty = threadIdx.y;   // 32 x 8
#pragma unroll
    for (int yy = 0; yy < 32; yy += 8)
        tile[ty + yy][tx] = x[((size_t)b * CC + c0 + ty + yy) * NP + n0 + tx];
    __syncthreads();
#pragma unroll
    for (int yy = 0; yy < 32; yy += 8) {
        float v = tile[tx][ty + yy];
        size_t off = ((size_t)b * NP + n0 + ty + yy) * CC + c0 + tx;
        g_xt[off] = v;
        __nv_bfloat16 h = __float2bfloat16(v);
        g_xhi[off] = h;
        g_xlo[off] = __float2bfloat16(v - __bfloat162float(h));
    }
}

// ---------------- K0b: negated half squared norms ----------------
__global__ void k_norm() {
    int p = blockIdx.x * blockDim.x + threadIdx.x;
    const float4* v = (const float4*)&g_xt[(size_t)p * CC];
    float s = 0.f;
#pragma unroll
    for (int i = 0; i < 16; i++) {
        float4 q = v[i];
        s += q.x * q.x + q.y * q.y + q.z * q.z + q.w * q.w;
    }
    g_xxn[p] = -0.5f * s;
}

// ---------------- K1: precompute U, V, Q per point ----------------
__global__ __launch_bounds__(256) void k_uvq(const float* __restrict__ W1,
                                             const float* __restrict__ W2) {
    __shared__ float xts[16][64];
    int p0 = blockIdx.x * 16;
    int o  = threadIdx.x;
    for (int s = threadIdx.x; s < 16 * 64; s += 256)
        xts[s >> 6][s & 63] = g_xt[(size_t)p0 * 64 + s];

    float4 wr[16];
    if (o < 64) {
        const float* r = W1 + o * 128;
#pragma unroll
        for (int i = 0; i < 16; i++)
            wr[i] = make_float4(r[4*i], r[4*i+1], r[4*i+2], r[4*i+3]);
    } else if (o < 128) {
        const float* r = W1 + (o - 64) * 128;
#pragma unroll
        for (int i = 0; i < 16; i++)
            wr[i] = make_float4(r[64+4*i]-r[4*i], r[65+4*i]-r[4*i+1],
                                r[66+4*i]-r[4*i+2], r[67+4*i]-r[4*i+3]);
    } else {
        const float* r = W2 + (o - 128) * 128;
#pragma unroll
        for (int i = 0; i < 16; i++)
            wr[i] = make_float4(r[64+4*i]-r[4*i], r[65+4*i]-r[4*i+1],
                                r[66+4*i]-r[4*i+2], r[67+4*i]-r[4*i+3]);
    }
    __syncthreads();

    float acc[16];
#pragma unroll
    for (int p = 0; p < 16; p++) acc[p] = 0.f;
#pragma unroll
    for (int c4 = 0; c4 < 16; c4++) {
        float4 w = wr[c4];
#pragma unroll
        for (int p = 0; p < 16; p++) {
            float4 xv = *(const float4*)&xts[p][c4 * 4];
            acc[p] += w.x * xv.x + w.y * xv.y + w.z * xv.z + w.w * xv.w;
        }
    }
#pragma unroll
    for (int p = 0; p < 16; p++)
        g_uvq[((size_t)p0 + p) * 256 + o] = acc[p];
}

// ---------------- K2: kNN top-20 via HMMA bf16 split-GEMM ----------------
// dot = Ahi.Bhi + Ahi.Blo + Alo.Bhi + Alo.Blo (full split, ~2^-26 rel err)
// rank = dot - 0.5*xx_j. j processed in two 64-col halves (acc = 32 regs).
#define SA_HI 0          // 128 x 128B = 16384
#define SA_LO 16384
#define SB_HI 32768
#define SB_LO 49152
#define SXXN  65536      // 512 B
#define KNN_SMEM_BYTES 81920   // merge phase: cv 40960 @0, ci 40960 @40960

#define INSL(bvA, biA, mvA, mpA, val, jj)                               \
    do {                                                                \
        float _v = (val);                                               \
        if (_v > mvA) {                                                 \
            bvA[mpA] = _v; biA[mpA] = (jj);                             \
            mvA = bvA[0]; mpA = 0;                                      \
            for (int _t = 1; _t < KNN; _t++)                            \
                if (bvA[_t] < mvA) { mvA = bvA[_t]; mpA = _t; }         \
        }                                                               \
    } while (0)

// load a 128-row x 64-col bf16 tile (128B rows, SW128) into smem
__device__ __forceinline__ void load_tile_bf16(char* dst,
                                               const __nv_bfloat16* src,
                                               int t0) {
    for (int ch = t0; ch < 1024; ch += 256) {
        int row = ch >> 3, c16 = ch & 7;
        uint4 v = *(const uint4*)(src + (size_t)row * 64 + c16 * 8);
        uint32_t off = row * 128 + c16 * 16;
        *(uint4*)(dst + SWZ(off)) = v;
    }
}

__global__ void __launch_bounds__(256, 2) k_knn() {
    extern __shared__ char sm[];
    uint32_t smb;
    asm("{ .reg .u64 t; cvta.to.shared.u64 t, %1; cvt.u32.u64 %0, t; }"
        : "=r"(smb) : "l"(sm));

    int b    = blockIdx.y;
    int i0   = blockIdx.x * 128;
    int tid  = threadIdx.x;
    int wid  = tid >> 5;
    int lane = tid & 31;
    size_t base = (size_t)b * NP;

    // A tiles (hi+lo), resident all kernel
    load_tile_bf16(sm + SA_HI, g_xhi + (base + i0) * CC, tid);
    load_tile_bf16(sm + SA_LO, g_xlo + (base + i0) * CC, tid);

    // ldmatrix lane addressing, swizzle hoisted:
    // SWZ(row*128 + c) = row*128 + (c ^ ((row&7)<<4))   for c < 128
    int a_row  = 16 * wid + (lane & 7) + 8 * ((lane >> 3) & 1);
    int a_coff = (lane >> 4) * 16;              // a_k8*2
    uint32_t a_mask = (a_row & 7) << 4;
    uint32_t ahi_base = smb + SA_HI + a_row * 128;
    uint32_t alo_base = smb + SA_LO + a_row * 128;

    int b_row  = (lane & 7) + 8 * (lane >> 4);  // j-col within 16-group
    int b_coff = ((lane >> 3) & 1) * 16;        // b_k8*2
    uint32_t b_mask = (b_row & 7) << 4;

    float bv0[KNN], bv1[KNN]; int bi0[KNN], bi1[KNN];
    float mv0 = -3.4e38f, mv1 = -3.4e38f; int mp0 = 0, mp1 = 0;
    for (int t = 0; t < KNN; t++) {
        bv0[t] = -3.4e38f; bi0[t] = 0;
        bv1[t] = -3.4e38f; bi1[t] = 0;
    }

    const float* xxn = (const float*)(sm + SXXN);
    int ncol = 2 * (lane & 3);

    for (int t = 0; t < 64; t++) {
        __syncthreads();
        load_tile_bf16(sm + SB_HI, g_xhi + (base + (size_t)t * 128) * CC, tid);
        load_tile_bf16(sm + SB_LO, g_xlo + (base + (size_t)t * 128) * CC, tid);
        if (tid < 32)
            *(float4*)(sm + SXXN + 16 * tid) =
                *(const float4*)&g_xxn[base + (size_t)t * 128 + 4 * tid];
        __syncthreads();

#pragma unroll
        for (int half = 0; half < 2; half++) {
            float acc[8][4];
#pragma unroll
            for (int n = 0; n < 8; n++)
#pragma unroll
                for (int q = 0; q < 4; q++) acc[n][q] = 0.f;

#pragma unroll
            for (int kk = 0; kk < 4; kk++) {
                uint32_t ahi[4], alo[4];
                uint32_t ac = (uint32_t)(32 * kk + a_coff) ^ a_mask;
                ldsm_x4(ahi, ahi_base + ac);
                ldsm_x4(alo, alo_base + ac);
#pragma unroll
                for (int p = 0; p < 4; p++) {
                    uint32_t bh[4], bl[4];
                    int j_loc = 64 * half + 16 * p + b_row;
                    uint32_t boff = (uint32_t)(j_loc * 128) +
                                    (((uint32_t)(32 * kk + b_coff)) ^ b_mask);
                    ldsm_x4(bh, smb + SB_HI + boff);
                    ldsm_x4(bl, smb + SB_LO + boff);
                    mma16816(acc[2 * p],     ahi, bh[0], bh[1]);
                    mma16816(acc[2 * p + 1], ahi, bh[2], bh[3]);
                    mma16816(acc[2 * p],     ahi, bl[0], bl[1]);
                    mma16816(acc[2 * p + 1], ahi, bl[2], bl[3]);
                    mma16816(acc[2 * p],     alo, bh[0], bh[1]);
                    mma16816(acc[2 * p + 1], alo, bh[2], bh[3]);
                    mma16816(acc[2 * p],     alo, bl[0], bl[1]);
                    mma16816(acc[2 * p + 1], alo, bl[2], bl[3]);
                }
            }

            // rank + insert straight from fragments
            int jh = t * 128 + 64 * half;
#pragma unroll
            for (int n = 0; n < 8; n++) {
                float2 nx = *(const float2*)&xxn[64 * half + 8 * n + ncol];
                int jc = jh + 8 * n + ncol;
                float v0 = acc[n][0] + nx.x;
                float v1 = acc[n][1] + nx.y;
                float v2 = acc[n][2] + nx.x;
                float v3 = acc[n][3] + nx.y;
                if (fmaxf(v0, v1) > mv0) {
                    INSL(bv0, bi0, mv0, mp0, v0, jc);
                    INSL(bv0, bi0, mv0, mp0, v1, jc + 1);
                }
                if (fmaxf(v2, v3) > mv1) {
                    INSL(bv1, bi1, mv1, mp1, v2, jc);
                    INSL(bv1, bi1, mv1, mp1, v3, jc + 1);
                }
            }
        }
    }

    // merge: 4 sub-lists per row -> exact top-20
    __syncthreads();
    float* cv = (float*)sm;              // 128 rows x 4 lists x 20
    int*   ci = (int*)(sm + 40960);
    {
        int r0 = 16 * wid + (lane >> 2);
        int r1 = r0 + 8;
        int s  = lane & 3;
        for (int t = 0; t < KNN; t++) {
            cv[(r0 * 4 + s) * KNN + t] = bv0[t];
            ci[(r0 * 4 + s) * KNN + t] = bi0[t];
            cv[(r1 * 4 + s) * KNN + t] = bv1[t];
            ci[(r1 * 4 + s) * KNN + t] = bi1[t];
        }
    }
    __syncthreads();
    if (tid < 128) {
        float fv[KNN]; int fi[KNN];
        float mv = -3.4e38f; int mp = 0;
        for (int t = 0; t < KNN; t++) { fv[t] = -3.4e38f; fi[t] = 0; }
        for (int u = 0; u < 4; u++) {
            int src = (tid * 4 + u) * KNN;
            for (int t = 0; t < KNN; t++) {
                float v = cv[src + t];
                if (v > mv) {
                    fv[mp] = v; fi[mp] = ci[src + t];
                    mv = fv[0]; mp = 0;
                    for (int w = 1; w < KNN; w++)
                        if (fv[w] < mv) { mv = fv[w]; mp = w; }
                }
            }
        }
        for (int t = 0; t < KNN; t++)
            g_idx[(base + i0 + tid) * KNN + t] = fi[t];
    }
}

// ---------------- K3: fused gather + softmax gate + output GEMM ----------------
__global__ __launch_bounds__(256) void k_fuse(const float* __restrict__ W2,
                                              float* __restrict__ out) {
    __shared__ float w2as[64 * 128];
    __shared__ float t_s[16][64];
    __shared__ int   idxs[16][KNN];

    int blk = blockIdx.x;
    int b   = blk >> 9;
    int n0  = (blk & 511) * 16;
    int tid = threadIdx.x;
    size_t base = (size_t)b * NP;

    for (int s = tid; s < 8192; s += 256) {
        int o = s >> 6, c = s & 63;
        w2as[c * 128 + o] = W2[o * 128 + c];
    }
    for (int s = tid; s < 16 * KNN; s += 256)
        idxs[s / KNN][s % KNN] = g_idx[(base + n0) * KNN + s];
    __syncthreads();

    for (int pass = 0; pass < 4; pass++) {
        int pt = pass * 4 + (tid >> 6);
        int d  = tid & 63;
        float vv = g_uvq[(base + n0 + pt) * 256 + 64 + d];
        float h[KNN];
#pragma unroll
        for (int k = 0; k < KNN; k++) {
            int j = idxs[pt][k];
            h[k] = g_uvq[(base + j) * 256 + d] + vv;
        }
        float m = h[0];
#pragma unroll
        for (int k = 1; k < KNN; k++) m = fmaxf(m, h[k]);
        float S = 0.f, ws = 0.f;
#pragma unroll
        for (int k = 0; k < KNN; k++) {
            float e = __expf(h[k] - m);
            S += e;
            int j = idxs[pt][k];
            ws += g_xt[(base + j) * 64 + d] * e;
        }
        t_s[pt][d] = ws / S;
    }
    __syncthreads();

    int o = tid & 127, g = tid >> 7;
    float acc[8];
#pragma unroll
    for (int p = 0; p < 8; p++)
        acc[p] = g_uvq[(base + n0 + g * 8 + p) * 256 + 128 + o];
#pragma unroll 8
    for (int c = 0; c < 64; c++) {
        float w = w2as[c * 128 + o];
#pragma unroll
        for (int p = 0; p < 8; p++) acc[p] += w * t_s[g * 8 + p][c];
    }
    float* op = out + ((size_t)b * OO + o) * NP + n0 + g * 8;
    *(float4*)op       = make_float4(acc[0], acc[1], acc[2], acc[3]);
    *(float4*)(op + 4) = make_float4(acc[4], acc[5], acc[6], acc[7]);
}

// ---------------- launch ----------------
extern "C" void kernel_launch(void* const* d_in, const int* in_sizes, int n_in,
                              void* d_out, int out_size) {
    const float* x  = (const float*)d_in[0];
    const float* W1 = (const float*)d_in[1];
    const float* W2 = (const float*)d_in[2];
    float* out = (float*)d_out;

    cudaFuncSetAttribute(k_knn, cudaFuncAttributeMaxDynamicSharedMemorySize,
                         KNN_SMEM_BYTES);

    k_transpose<<<dim3(NP / 32, CC / 32, BB), dim3(32, 8)>>>(x);
    k_norm<<<(BB * NP) / 256, 256>>>();
    k_uvq<<<(BB * NP) / 16, 256>>>(W1, W2);
    k_knn<<<dim3(NP / 128, BB), 256, KNN_SMEM_BYTES>>>();
    k_fuse<<<(BB * NP) / 16, 256>>>(W2, out);
}